// round 2
// baseline (speedup 1.0000x reference)
#include <cuda_runtime.h>
#include <cstdint>

// gcc_Conv2d_64347200028713 as batched circulant GEMM on tensor cores.
// out[b,c,h,w] = bias[c] + sum_k w[c,(k-h)%56] * x[b,c,k,w]
//   -> per (b,c): D[56,56] = M_c[56,56] @ X[56,56]
// mma.sync.m16n8k8.tf32 with 3xTF32 split (M_hi@X_hi + M_lo@X_hi + M_hi@X_lo)
// for fp32-class accuracy. Block = (channel, 4 batches), 8 warps.

#define CCH 384
#define HH 56
#define WW 56
#define PLANE (HH * WW)        // 3136
#define NBAT 4                 // batches per block
#define XSTR 72                // smem row stride in words (72 % 32 == 8 -> conflict-free)
#define XPLANE (HH * XSTR)     // 4032 words per plane
#define NTHREADS 256
#define SMEM_BYTES ((NBAT * XPLANE + 128) * 4)   // 65024 B

__device__ __forceinline__ uint32_t f2tf32(float x) {
    uint32_t r;
    asm("cvt.rna.tf32.f32 %0, %1;" : "=r"(r) : "f"(x));
    return r;
}

__device__ __forceinline__ void mma_tf32(float c[4], const uint32_t a[4],
                                         uint32_t b0, uint32_t b1) {
    asm("mma.sync.aligned.m16n8k8.row.col.f32.tf32.tf32.f32 "
        "{%0,%1,%2,%3}, {%4,%5,%6,%7}, {%8,%9}, {%0,%1,%2,%3};"
        : "+f"(c[0]), "+f"(c[1]), "+f"(c[2]), "+f"(c[3])
        : "r"(a[0]), "r"(a[1]), "r"(a[2]), "r"(a[3]), "r"(b0), "r"(b1));
}

extern __shared__ float sm[];

__global__ __launch_bounds__(NTHREADS, 2)
void gcc_conv_mma(const float* __restrict__ x, const float* __restrict__ weight,
                  const float* __restrict__ bias, float* __restrict__ out) {
    float* s_x  = sm;                      // [NBAT][56][XSTR] raw fp32 planes
    float* s_wh = sm + NBAT * XPLANE;      // [56] tf32-rounded weight (as f32 bits)
    float* s_wl = s_wh + 64;               // [56] tf32 residual

    const int blk = blockIdx.x;
    const int c   = blk % CCH;
    const int b0  = (blk / CCH) * NBAT;
    const int tid = threadIdx.x;

    // ---- stage 4 x-planes into smem (fp32, padded stride) ----
    for (int i = tid; i < NBAT * (PLANE / 4); i += NTHREADS) {
        int p  = i / (PLANE / 4);
        int r4 = i % (PLANE / 4);          // float4 index within plane
        int row = r4 / (WW / 4);
        int c4  = r4 % (WW / 4);
        float4 v = ((const float4*)(x + (((size_t)(b0 + p)) * CCH + c) * PLANE))[r4];
        *(float4*)&s_x[p * XPLANE + row * XSTR + c4 * 4] = v;
    }
    // ---- weight hi/lo tables ----
    if (tid < HH) {
        float v = weight[c * HH + tid];
        uint32_t hu = f2tf32(v);
        float hf = __uint_as_float(hu);
        s_wh[tid] = hf;
        s_wl[tid] = __uint_as_float(f2tf32(v - hf));
    }
    const float bv = bias[c];
    __syncthreads();

    const int wid  = tid >> 5;
    const int lane = tid & 31;
    const int mp   = wid >> 2;             // m-pair: rows [32*mp, 32*mp+32)
    const int bat  = wid & 3;              // which batch plane this warp handles
    const int g    = lane >> 2;            // group id (0..7)
    const int tig  = lane & 3;             // thread in group (0..3)

    // accumulators: [m-tile within pair][n-tile][frag]
    float acc[2][7][4];
#pragma unroll
    for (int t = 0; t < 2; t++)
#pragma unroll
        for (int j = 0; j < 7; j++)
#pragma unroll
            for (int r = 0; r < 4; r++) acc[t][j][r] = bv;

    // A-index bases: A[m][k] = w[(k - m) mod 56]; fragment rows m = base+g, base+g+8
    int offA[2][2];
#pragma unroll
    for (int t = 0; t < 2; t++) {
        int r0 = 32 * mp + 16 * t + g;
        offA[t][0] = ((tig - r0) % 56 + 56) % 56;
        offA[t][1] = ((tig - r0 - 8) % 56 + 56) % 56;
    }

    const float* s_xb = s_x + bat * XPLANE;

    // ---- 3 K-segments: (M_hi,X_hi), (M_lo,X_hi), (M_hi,X_lo) ----
#pragma unroll
    for (int seg = 0; seg < 3; seg++) {
        const uint32_t* wt = (const uint32_t*)((seg == 1) ? s_wl : s_wh);
        const bool lo = (seg == 2);
#pragma unroll 1
        for (int ks = 0; ks < 7; ks++) {
            const int koff = ks * 8;
            uint32_t a[2][4];
#pragma unroll
            for (int t = 0; t < 2; t++) {
                int i0 = offA[t][0] + koff;        // (row g,   col tig)
                int i1 = offA[t][1] + koff;        // (row g+8, col tig)
                int i2 = i0 + 4;                   // (row g,   col tig+4)
                int i3 = i1 + 4;                   // (row g+8, col tig+4)
                if (i0 >= 56) i0 -= 56;
                if (i1 >= 56) i1 -= 56;
                if (i2 >= 56) i2 -= 56;
                if (i3 >= 56) i3 -= 56;
                a[t][0] = wt[i0];
                a[t][1] = wt[i1];
                a[t][2] = wt[i2];
                a[t][3] = wt[i3];
            }
            const float* xk0 = s_xb + (koff + tig) * XSTR;
            const float* xk1 = xk0 + 4 * XSTR;
#pragma unroll
            for (int j = 0; j < 7; j++) {
                float x0 = xk0[8 * j + g];
                float x1 = xk1[8 * j + g];
                uint32_t b0, b1;
                if (!lo) {
                    b0 = f2tf32(x0);
                    b1 = f2tf32(x1);
                } else {
                    uint32_t h0 = f2tf32(x0), h1 = f2tf32(x1);
                    b0 = f2tf32(x0 - __uint_as_float(h0));
                    b1 = f2tf32(x1 - __uint_as_float(h1));
                }
                mma_tf32(acc[0][j], a[0], b0, b1);
                mma_tf32(acc[1][j], a[1], b0, b1);
            }
        }
    }

    // ---- epilogue: D rows base+g and base+g+8, cols 8j+2*tig(+1) ----
    float* op = out + ((size_t)(b0 + bat) * CCH + c) * PLANE;
#pragma unroll
    for (int t = 0; t < 2; t++) {
        const int r0 = 32 * mp + 16 * t + g;       // always < 56
        const int r1 = r0 + 8;                     // >= 56 only for mp=1,t=1 (padding)
#pragma unroll
        for (int j = 0; j < 7; j++) {
            const int col = 8 * j + 2 * tig;
            float2 v01 = make_float2(acc[t][j][0], acc[t][j][1]);
            *(float2*)&op[r0 * WW + col] = v01;
            if (r1 < HH) {
                float2 v23 = make_float2(acc[t][j][2], acc[t][j][3]);
                *(float2*)&op[r1 * WW + col] = v23;
            }
        }
    }
}

extern "C" void kernel_launch(void* const* d_in, const int* in_sizes, int n_in,
                              void* d_out, int out_size) {
    const float* x      = (const float*)d_in[0];   // [32,384,56,56]
    const float* weight = (const float*)d_in[1];   // [384,1,56,1]
    const float* bias   = (const float*)d_in[2];   // [384]
    float* out = (float*)d_out;

    cudaFuncSetAttribute(gcc_conv_mma,
                         cudaFuncAttributeMaxDynamicSharedMemorySize, SMEM_BYTES);
    const int nblocks = CCH * (32 / NBAT);         // 384 * 8 = 3072
    gcc_conv_mma<<<nblocks, NTHREADS, SMEM_BYTES>>>(x, weight, bias, out);
}

// round 3
// speedup vs baseline: 1.0074x; 1.0074x over previous
#include <cuda_runtime.h>
#include <cstdint>

// gcc_Conv2d_64347200028713 as batched circulant GEMM on tensor cores.
// out[b,c,h,w] = bias[c] + sum_k w[c,(k-h)%56] * x[b,c,k,w]
//   -> per (b,c): D[56,56] = M_c[56,56] @ X[56,56]
// mma.sync.m16n8k8.tf32 with 3xTF32 split (M_hi@X_hi + M_lo@X_hi + M_hi@X_lo)
// for fp32-class accuracy. Block = (channel, 4 batches), 8 warps.

#define CCH 384
#define HH 56
#define WW 56
#define PLANE (HH * WW)        // 3136
#define NBAT 4                 // batches per block
#define XSTR 72                // smem row stride in words (72 % 32 == 8 -> conflict-free)
#define XPLANE (HH * XSTR)     // 4032 words per plane
#define NTHREADS 256
#define SMEM_BYTES ((NBAT * XPLANE + 128) * 4)   // 65024 B

__device__ __forceinline__ uint32_t f2tf32(float x) {
    uint32_t r;
    asm("cvt.rna.tf32.f32 %0, %1;" : "=r"(r) : "f"(x));
    return r;
}

__device__ __forceinline__ void mma_tf32(float c[4], const uint32_t a[4],
                                         uint32_t b0, uint32_t b1) {
    asm("mma.sync.aligned.m16n8k8.row.col.f32.tf32.tf32.f32 "
        "{%0,%1,%2,%3}, {%4,%5,%6,%7}, {%8,%9}, {%0,%1,%2,%3};"
        : "+f"(c[0]), "+f"(c[1]), "+f"(c[2]), "+f"(c[3])
        : "r"(a[0]), "r"(a[1]), "r"(a[2]), "r"(a[3]), "r"(b0), "r"(b1));
}

extern __shared__ float sm[];

__global__ __launch_bounds__(NTHREADS, 2)
void gcc_conv_mma(const float* __restrict__ x, const float* __restrict__ weight,
                  const float* __restrict__ bias, float* __restrict__ out) {
    float* s_x  = sm;                      // [NBAT][56][XSTR] raw fp32 planes
    float* s_wh = sm + NBAT * XPLANE;      // [56] tf32-rounded weight (as f32 bits)
    float* s_wl = s_wh + 64;               // [56] tf32 residual

    const int blk = blockIdx.x;
    const int c   = blk % CCH;
    const int b0  = (blk / CCH) * NBAT;
    const int tid = threadIdx.x;

    // ---- stage 4 x-planes into smem (fp32, padded stride) ----
    for (int i = tid; i < NBAT * (PLANE / 4); i += NTHREADS) {
        int p  = i / (PLANE / 4);
        int r4 = i % (PLANE / 4);          // float4 index within plane
        int row = r4 / (WW / 4);
        int c4  = r4 % (WW / 4);
        float4 v = ((const float4*)(x + (((size_t)(b0 + p)) * CCH + c) * PLANE))[r4];
        *(float4*)&s_x[p * XPLANE + row * XSTR + c4 * 4] = v;
    }
    // ---- weight hi/lo tables ----
    if (tid < HH) {
        float v = weight[c * HH + tid];
        uint32_t hu = f2tf32(v);
        float hf = __uint_as_float(hu);
        s_wh[tid] = hf;
        s_wl[tid] = __uint_as_float(f2tf32(v - hf));
    }
    const float bv = bias[c];
    __syncthreads();

    const int wid  = tid >> 5;
    const int lane = tid & 31;
    const int mp   = wid >> 2;             // m-pair: rows [32*mp, 32*mp+32)
    const int bat  = wid & 3;              // which batch plane this warp handles
    const int g    = lane >> 2;            // group id (0..7)
    const int tig  = lane & 3;             // thread in group (0..3)

    // accumulators: [m-tile within pair][n-tile][frag]
    float acc[2][7][4];
#pragma unroll
    for (int t = 0; t < 2; t++)
#pragma unroll
        for (int j = 0; j < 7; j++)
#pragma unroll
            for (int r = 0; r < 4; r++) acc[t][j][r] = bv;

    // A-index bases: A[m][k] = w[(k - m) mod 56]; fragment rows m = base+g, base+g+8
    int offA[2][2];
#pragma unroll
    for (int t = 0; t < 2; t++) {
        int r0 = 32 * mp + 16 * t + g;
        offA[t][0] = ((tig - r0) % 56 + 56) % 56;
        offA[t][1] = ((tig - r0 - 8) % 56 + 56) % 56;
    }

    const float* s_xb = s_x + bat * XPLANE;

    // ---- 3 K-segments: (M_hi,X_hi), (M_lo,X_hi), (M_hi,X_lo) ----
#pragma unroll
    for (int seg = 0; seg < 3; seg++) {
        const uint32_t* wt = (const uint32_t*)((seg == 1) ? s_wl : s_wh);
        const bool lo = (seg == 2);
#pragma unroll 1
        for (int ks = 0; ks < 7; ks++) {
            const int koff = ks * 8;
            uint32_t a[2][4];
#pragma unroll
            for (int t = 0; t < 2; t++) {
                int i0 = offA[t][0] + koff;        // (row g,   col tig)
                int i1 = offA[t][1] + koff;        // (row g+8, col tig)
                int i2 = i0 + 4;                   // (row g,   col tig+4)
                int i3 = i1 + 4;                   // (row g+8, col tig+4)
                if (i0 >= 56) i0 -= 56;
                if (i1 >= 56) i1 -= 56;
                if (i2 >= 56) i2 -= 56;
                if (i3 >= 56) i3 -= 56;
                a[t][0] = wt[i0];
                a[t][1] = wt[i1];
                a[t][2] = wt[i2];
                a[t][3] = wt[i3];
            }
            const float* xk0 = s_xb + (koff + tig) * XSTR;
            const float* xk1 = xk0 + 4 * XSTR;
#pragma unroll
            for (int j = 0; j < 7; j++) {
                float x0 = xk0[8 * j + g];
                float x1 = xk1[8 * j + g];
                uint32_t b0, b1;
                if (!lo) {
                    b0 = f2tf32(x0);
                    b1 = f2tf32(x1);
                } else {
                    uint32_t h0 = f2tf32(x0), h1 = f2tf32(x1);
                    b0 = f2tf32(x0 - __uint_as_float(h0));
                    b1 = f2tf32(x1 - __uint_as_float(h1));
                }
                mma_tf32(acc[0][j], a[0], b0, b1);
                mma_tf32(acc[1][j], a[1], b0, b1);
            }
        }
    }

    // ---- epilogue: D rows base+g and base+g+8, cols 8j+2*tig(+1) ----
    float* op = out + ((size_t)(b0 + bat) * CCH + c) * PLANE;
#pragma unroll
    for (int t = 0; t < 2; t++) {
        const int r0 = 32 * mp + 16 * t + g;       // always < 56
        const int r1 = r0 + 8;                     // >= 56 only for mp=1,t=1 (padding)
#pragma unroll
        for (int j = 0; j < 7; j++) {
            const int col = 8 * j + 2 * tig;
            float2 v01 = make_float2(acc[t][j][0], acc[t][j][1]);
            *(float2*)&op[r0 * WW + col] = v01;
            if (r1 < HH) {
                float2 v23 = make_float2(acc[t][j][2], acc[t][j][3]);
                *(float2*)&op[r1 * WW + col] = v23;
            }
        }
    }
}

extern "C" void kernel_launch(void* const* d_in, const int* in_sizes, int n_in,
                              void* d_out, int out_size) {
    const float* x      = (const float*)d_in[0];   // [32,384,56,56]
    const float* weight = (const float*)d_in[1];   // [384,1,56,1]
    const float* bias   = (const float*)d_in[2];   // [384]
    float* out = (float*)d_out;

    cudaFuncSetAttribute(gcc_conv_mma,
                         cudaFuncAttributeMaxDynamicSharedMemorySize, SMEM_BYTES);
    const int nblocks = CCH * (32 / NBAT);         // 384 * 8 = 3072
    gcc_conv_mma<<<nblocks, NTHREADS, SMEM_BYTES>>>(x, weight, bias, out);
}

// round 5
// speedup vs baseline: 1.4793x; 1.4684x over previous
#include <cuda_runtime.h>
#include <cuda_bf16.h>
#include <cstdint>

// Circular depthwise conv as circulant GEMM on mma.sync.m16n8k16.bf16.
// Per channel c: D[56, n] = A_c[56,56] @ X[56, n], A_c[m,k] = w_c[(k-m)%56].
// bf16 3-term split: A_hi*B_hi + A_mid*B_hi + A_hi*B_mid (rel err ~1e-5).
// Block = (channel, 4 batches): M=64(pad), K=64(pad), N=224.
// A fragments in registers (built once); B stored in smem in fragment order
// by the convert pass, so each B fragment is one LDS.64.

#define CCH 384
#define HW 56
#define PLANE 3136
#define NB 4
#define NTT 28                    // n-tiles (224/8)
#define NTHREADS 256

#define KT_STRIDE (NTT * 256)     // 7168 B per k-tile
#define CH_STRIDE (4 * KT_STRIDE) // 28672 B per precision chunk
#define B_BYTES (2 * CH_STRIDE)   // 57344
#define W_OFF B_BYTES
#define SMEM_TOTAL (B_BYTES + 256)

__device__ __forceinline__ void mma_bf16(float c[4], const uint32_t a[4],
                                         uint2 b) {
    asm volatile(
        "mma.sync.aligned.m16n8k16.row.col.f32.bf16.bf16.f32 "
        "{%0,%1,%2,%3}, {%4,%5,%6,%7}, {%8,%9}, {%0,%1,%2,%3};"
        : "+f"(c[0]), "+f"(c[1]), "+f"(c[2]), "+f"(c[3])
        : "r"(a[0]), "r"(a[1]), "r"(a[2]), "r"(a[3]), "r"(b.x), "r"(b.y));
}

extern __shared__ char smem[];

__global__ __launch_bounds__(NTHREADS, 3)
void gcc_conv_hmma(const float* __restrict__ x, const float* __restrict__ weight,
                   const float* __restrict__ bias, float* __restrict__ out) {
    const int tid = threadIdx.x;
    const int c  = blockIdx.x >> 3;
    const int b0 = (blockIdx.x & 7) * NB;

    // weight table (fp32)
    float* wtab = (float*)(smem + W_OFF);
    if (tid < HW) wtab[tid] = weight[c * HW + tid];

    // zero the K-pad B slots (k=56..63 => kt=3, word 1) once; never rewritten
    for (int i = tid; i < 2 * NTT * 32; i += NTHREADS) {
        int ch = i / (NTT * 32), r = i % (NTT * 32);
        *(uint32_t*)(smem + ch * CH_STRIDE + 3 * KT_STRIDE + r * 8 + 4) = 0u;
    }
    __syncthreads();

    const int wid = tid >> 5, lane = tid & 31;
    const int wm = wid & 3, wn = wid >> 1 & 0 ? 0 : (wid >> 2);  // wn = wid>>2
    const int g = lane >> 2, i4 = lane & 3;
    const int r0 = wm * 16 + g;            // < 56 always
    const int r1 = r0 + 8;                 // >= 56 only when wm==3

    // ---- build A fragments in registers: Ah/Am [kt][reg] ----
    uint32_t Ah[4][4], Am[4][4];
#pragma unroll
    for (int kt = 0; kt < 4; kt++) {
        const int kbase = kt * 16 + 2 * i4;
#pragma unroll
        for (int reg = 0; reg < 4; reg++) {
            const int row = (reg & 1) ? r1 : r0;
            const int kk = kbase + ((reg & 2) ? 8 : 0);
            float v0 = 0.f, v1 = 0.f;
            if (kk < HW && row < HW) {
                int j0 = kk - row;     if (j0 < 0) j0 += HW;
                int j1 = kk + 1 - row; if (j1 < 0) j1 += HW;
                v0 = wtab[j0];
                v1 = wtab[j1];
            }
            __nv_bfloat162 h = __floats2bfloat162_rn(v0, v1);
            float m0 = v0 - __bfloat162float(h.x);
            float m1 = v1 - __bfloat162float(h.y);
            __nv_bfloat162 m = __floats2bfloat162_rn(m0, m1);
            Ah[kt][reg] = *(uint32_t*)&h;
            Am[kt][reg] = *(uint32_t*)&m;
        }
    }

    // ---- load + split-convert X into fragment-ordered smem ----
    // unit: (batch b, k-pair kp, w-quad wq); 4*28*14 = 1568 units
    for (int u = tid; u < NB * 28 * 14; u += NTHREADS) {
        const int b = u / 392, rem = u % 392;
        const int kp = rem / 14, wq = rem % 14;
        const int k = kp * 2, w = wq * 4;
        const float4* p = (const float4*)(x + ((size_t)(b0 + b) * CCH + c) * PLANE
                                          + k * HW + w);
        const float4 v0 = p[0];     // row k
        const float4 v1 = p[14];    // row k+1
        const int n0 = b * HW + w;
        const int nt = n0 >> 3, nl = n0 & 7;
        const int kt = k >> 4, kq = (k & 7) >> 1, word = ((k & 15) >= 8);
        char* base = smem + kt * KT_STRIDE + nt * 256 + kq * 8 + word * 4;
        const float a[4] = {v0.x, v0.y, v0.z, v0.w};
        const float d[4] = {v1.x, v1.y, v1.z, v1.w};
#pragma unroll
        for (int j = 0; j < 4; j++) {
            __nv_bfloat162 h = __floats2bfloat162_rn(a[j], d[j]);
            float m0 = a[j] - __bfloat162float(h.x);
            float m1 = d[j] - __bfloat162float(h.y);
            __nv_bfloat162 m = __floats2bfloat162_rn(m0, m1);
            *(uint32_t*)(base + (nl + j) * 32) = *(uint32_t*)&h;
            *(uint32_t*)(base + CH_STRIDE + (nl + j) * 32) = *(uint32_t*)&m;
        }
    }
    __syncthreads();

    // ---- MMA + store: each warp: m rows [16wm,16wm+16), n-tiles [14wn,14wn+14) ----
    const float bv = bias[c];
#pragma unroll
    for (int np = 0; np < 7; np++) {
        const int nt0 = (wid >> 2) * 14 + np * 2;
        float acc0[4] = {bv, bv, bv, bv};
        float acc1[4] = {bv, bv, bv, bv};
        const char* bp0 = smem + nt0 * 256 + lane * 8;
        const char* bp1 = bp0 + 256;
#pragma unroll
        for (int kt = 0; kt < 4; kt++) {
            const uint2 bh0 = *(const uint2*)(bp0 + kt * KT_STRIDE);
            const uint2 bh1 = *(const uint2*)(bp1 + kt * KT_STRIDE);
            const uint2 bm0 = *(const uint2*)(bp0 + CH_STRIDE + kt * KT_STRIDE);
            const uint2 bm1 = *(const uint2*)(bp1 + CH_STRIDE + kt * KT_STRIDE);
            mma_bf16(acc0, Ah[kt], bh0);
            mma_bf16(acc1, Ah[kt], bh1);
            mma_bf16(acc0, Am[kt], bh0);
            mma_bf16(acc1, Am[kt], bh1);
            mma_bf16(acc0, Ah[kt], bm0);
            mma_bf16(acc1, Ah[kt], bm1);
        }
        // epilogue: rows r0 (c0,c1) and r1 (c2,c3), cols nt*8 + 2*i4
#pragma unroll
        for (int s = 0; s < 2; s++) {
            const int nt = nt0 + s;
            const float* acc = s ? acc1 : acc0;
            const int n = nt * 8 + 2 * i4;
            const int b = n / HW, wcol = n % HW;
            float* op = out + ((size_t)(b0 + b) * CCH + c) * PLANE + wcol;
            *(float2*)(op + r0 * HW) = make_float2(acc[0], acc[1]);
            if (wm != 3)
                *(float2*)(op + r1 * HW) = make_float2(acc[2], acc[3]);
        }
    }
}

extern "C" void kernel_launch(void* const* d_in, const int* in_sizes, int n_in,
                              void* d_out, int out_size) {
    const float* x      = (const float*)d_in[0];
    const float* weight = (const float*)d_in[1];
    const float* bias   = (const float*)d_in[2];
    cudaFuncSetAttribute(gcc_conv_hmma,
                         cudaFuncAttributeMaxDynamicSharedMemorySize, SMEM_TOTAL);
    gcc_conv_hmma<<<CCH * 8, NTHREADS, SMEM_TOTAL>>>(x, weight, bias, (float*)d_out);
}

// round 6
// speedup vs baseline: 2.2317x; 1.5086x over previous
#include <cuda_runtime.h>
#include <cuda_bf16.h>
#include <cstdint>

// Circular depthwise conv as circulant GEMM on mma.sync.m16n8k16.bf16.
// D[56,224] = A_c[56,56(pad64)] @ X[56(pad64),224] per (channel, 4 batches).
// 3-term bf16 split: Ah*Bh + Am*Bh + Ah*Bm.
// B staged in smem in natural [k][n] bf16 layout (conflict-free STS.64),
// fragments fetched with ldmatrix.m8n8.x4.trans. A frags in registers.

#define CCH 384
#define HW 56
#define PLANE 3136
#define NTHREADS 256
#define ROWB 496                     // bytes per k-row (124 words; 124%32==28)
#define CH_STRIDE (64 * ROWB)        // 31744 B per precision chunk
#define W_OFF (2 * CH_STRIDE)        // 63488
#define SMEM_TOTAL (W_OFF + 256)     // 63744

__device__ __forceinline__ uint32_t smem_u32(const void* p) {
    uint32_t a;
    asm("{ .reg .u64 t; cvta.to.shared.u64 t, %1; cvt.u32.u64 %0, t; }" : "=r"(a) : "l"(p));
    return a;
}
__device__ __forceinline__ void ldmat4t(uint32_t r[4], uint32_t addr) {
    asm volatile("ldmatrix.sync.aligned.m8n8.x4.trans.shared.b16 {%0,%1,%2,%3}, [%4];"
                 : "=r"(r[0]), "=r"(r[1]), "=r"(r[2]), "=r"(r[3]) : "r"(addr));
}
__device__ __forceinline__ void mma_bf16(float c[4], const uint32_t a[4],
                                         uint32_t b0, uint32_t b1) {
    asm volatile(
        "mma.sync.aligned.m16n8k16.row.col.f32.bf16.bf16.f32 "
        "{%0,%1,%2,%3}, {%4,%5,%6,%7}, {%8,%9}, {%0,%1,%2,%3};"
        : "+f"(c[0]), "+f"(c[1]), "+f"(c[2]), "+f"(c[3])
        : "r"(a[0]), "r"(a[1]), "r"(a[2]), "r"(a[3]), "r"(b0), "r"(b1));
}
__device__ __forceinline__ uint32_t bits2(__nv_bfloat162 v) { return *(uint32_t*)&v; }

extern __shared__ char smem[];

__global__ __launch_bounds__(NTHREADS, 3)
void gcc_conv_hmma2(const float* __restrict__ x, const float* __restrict__ weight,
                    const float* __restrict__ bias, float* __restrict__ out) {
    const int tid = threadIdx.x;
    const int c  = blockIdx.x >> 3;
    const int b0 = (blockIdx.x & 7) * 4;

    float* wtab = (float*)(smem + W_OFF);
    if (tid < HW) wtab[tid] = weight[c * HW + tid];

    // zero K-pad rows 56..63 (both chunks); never rewritten
    for (int i = tid; i < 2 * 8 * (ROWB / 16); i += NTHREADS) {
        int ch = i / 248, j = i % 248;
        *(uint4*)(smem + ch * CH_STRIDE + 56 * ROWB + j * 16) = make_uint4(0, 0, 0, 0);
    }
    __syncthreads();

    const int wid = tid >> 5, lane = tid & 31;
    const int wm = wid & 3, wn = wid >> 2;
    const int g = lane >> 2, i4 = lane & 3;
    const int r0 = wm * 16 + g;          // < 56 always
    const int r1 = r0 + 8;               // >= 56 only when wm==3

    // ---- A circulant fragments in registers (hi / mid) ----
    uint32_t Ah[4][4], Am[4][4];
#pragma unroll
    for (int kt = 0; kt < 4; kt++) {
#pragma unroll
        for (int reg = 0; reg < 4; reg++) {
            const int row = (reg & 1) ? r1 : r0;
            const int kk = kt * 16 + 2 * i4 + ((reg & 2) ? 8 : 0);   // even
            float v0 = 0.f, v1 = 0.f;
            if (kk < HW && row < HW) {                               // kk even => kk+1<56 too
                int j0 = kk - row; if (j0 < 0) j0 += HW;
                int j1 = j0 + 1;   if (j1 == HW) j1 = 0;
                v0 = wtab[j0];
                v1 = wtab[j1];
            }
            __nv_bfloat162 h = __floats2bfloat162_rn(v0, v1);
            __nv_bfloat162 m = __floats2bfloat162_rn(v0 - __bfloat162float(h.x),
                                                     v1 - __bfloat162float(h.y));
            Ah[kt][reg] = bits2(h);
            Am[kt][reg] = bits2(m);
        }
    }

    // ---- load + split-convert X into natural [k][n] smem (hi & mid chunks) ----
    // unit = (b, k, wq): one float4 of row k, cols 4wq..4wq+3 of batch b0+b.
#pragma unroll 4
    for (int u = tid; u < 4 * HW * 14; u += NTHREADS) {
        const int b = u / 784;
        const int rem = u - b * 784;
        const int k = rem / 14;
        const int wq = rem - k * 14;
        const float4 v = *(const float4*)(x + ((size_t)(b0 + b) * CCH + c) * PLANE
                                          + k * HW + wq * 4);
        __nv_bfloat162 h01 = __floats2bfloat162_rn(v.x, v.y);
        __nv_bfloat162 h23 = __floats2bfloat162_rn(v.z, v.w);
        __nv_bfloat162 m01 = __floats2bfloat162_rn(v.x - __bfloat162float(h01.x),
                                                   v.y - __bfloat162float(h01.y));
        __nv_bfloat162 m23 = __floats2bfloat162_rn(v.z - __bfloat162float(h23.x),
                                                   v.w - __bfloat162float(h23.y));
        char* p = smem + k * ROWB + b * 112 + wq * 8;     // n = 56b + 4wq, bf16 idx
        *(uint2*)p = make_uint2(bits2(h01), bits2(h23));
        *(uint2*)(p + CH_STRIDE) = make_uint2(bits2(m01), bits2(m23));
    }
    __syncthreads();

    // ---- MMA: warp = (m-quarter wm, n-half wn); 7 n-tile pairs each ----
    const float bv = bias[c];
    const uint32_t sbase = smem_u32(smem);
    const int krow = (lane & 7) + ((lane >> 3) & 1) * 8;   // 0..15 within k-tile
    const int nsel = lane >> 4;                            // 0/1: n-tile in pair
    const uint32_t lbase = sbase + krow * ROWB;

#pragma unroll
    for (int np = 0; np < 7; np++) {
        const int nt0 = wn * 14 + np * 2;
        float acc0[4] = {bv, bv, bv, bv};
        float acc1[4] = {bv, bv, bv, bv};
        const uint32_t laddr = lbase + (uint32_t)(nt0 + nsel) * 16;
#pragma unroll
        for (int kt = 0; kt < 4; kt++) {
            uint32_t bh[4], bm[4];
            ldmat4t(bh, laddr + kt * 16 * ROWB);
            ldmat4t(bm, laddr + kt * 16 * ROWB + CH_STRIDE);
            mma_bf16(acc0, Ah[kt], bh[0], bh[1]);
            mma_bf16(acc1, Ah[kt], bh[2], bh[3]);
            mma_bf16(acc0, Am[kt], bh[0], bh[1]);
            mma_bf16(acc1, Am[kt], bh[2], bh[3]);
            mma_bf16(acc0, Ah[kt], bm[0], bm[1]);
            mma_bf16(acc1, Ah[kt], bm[2], bm[3]);
        }
#pragma unroll
        for (int s = 0; s < 2; s++) {
            const float* acc = s ? acc1 : acc0;
            const int n = (nt0 + s) * 8 + 2 * i4;
            const int b = n / HW, wcol = n - b * HW;
            float* op = out + ((size_t)(b0 + b) * CCH + c) * PLANE + wcol;
            *(float2*)(op + r0 * HW) = make_float2(acc[0], acc[1]);
            if (wm != 3)
                *(float2*)(op + r1 * HW) = make_float2(acc[2], acc[3]);
        }
    }
}

extern "C" void kernel_launch(void* const* d_in, const int* in_sizes, int n_in,
                              void* d_out, int out_size) {
    const float* x      = (const float*)d_in[0];
    const float* weight = (const float*)d_in[1];
    const float* bias   = (const float*)d_in[2];
    cudaFuncSetAttribute(gcc_conv_hmma2,
                         cudaFuncAttributeMaxDynamicSharedMemorySize, SMEM_TOTAL);
    gcc_conv_hmma2<<<CCH * 8, NTHREADS, SMEM_TOTAL>>>(x, weight, bias, (float*)d_out);
}